// round 11
// baseline (speedup 1.0000x reference)
#include <cuda_runtime.h>
#include <cuda_fp16.h>
#include <cstdint>
#include <math.h>

#define B_DIM 4096
#define IN_DIM 1024
#define H_DIM 1024
#define K_DIM 2048   // IN + H
#define N_DIM 4096   // 4*H, gate-interleaved: col n -> gate n&3, hidden n>>2

#define BM 128
#define BN 128
#define KC 64
#define NCHUNK (K_DIM / KC)     // 32
#define NKSTEP (K_DIM / 16)     // 128 total k16-steps

// A SMEM tile rows: 64 fp16 = 128B data + 16B pad = 144B (conflict-free
// 16B-lane pattern for ldmatrix and cp.async).
#define ROWB 144
#define ATILE (128 * ROWB)            // 18432 B per stage (A only)
#define NSTAGE 4
#define SMEM_TOTAL (NSTAGE * ATILE)   // 73728 B

// Epilogue smem (reuses pipeline smem): 3 x [128][CPAD] fp32 = 55296 B
#define CPAD 36

// ---------------------------------------------------------------------------
// Device scratch
// ---------------------------------------------------------------------------
__device__ __half g_A[(size_t)B_DIM * K_DIM];
// W in MMA-fragment-linear layout:
//   uint32 index o: jj=o&3, lane=(o>>2)&31, h2=(o>>7)&1, ks=(o>>8)&127, NB=o>>15
//   maps to W element pair (n, k),(n, k+1) with
//   n = NB*32 + h2*16 + (jj>>1)*8 + (lane>>2),  k = ks*16 + (jj&1)*8 + 2*(lane&3)
__device__ __half g_Wf[(size_t)N_DIM * K_DIM];
__device__ float g_biasp[N_DIM];

// ---------------------------------------------------------------------------
// PTX helpers (baseline PTX only: works on compute_103 virtual arch)
// ---------------------------------------------------------------------------
__device__ __forceinline__ uint32_t smem_u32(const void* p) {
    uint32_t a;
    asm("{ .reg .u64 t; cvta.to.shared.u64 t, %1; cvt.u32.u64 %0, t; }" : "=r"(a) : "l"(p));
    return a;
}
__device__ __forceinline__ void cp_async16(uint32_t dst, const void* src) {
    asm volatile("cp.async.cg.shared.global [%0], [%1], 16;" :: "r"(dst), "l"(src));
}
#define CP_COMMIT()  asm volatile("cp.async.commit_group;" ::: "memory")
#define CP_WAIT(N)   asm volatile("cp.async.wait_group %0;" :: "n"(N) : "memory")

__device__ __forceinline__ void ldsm4(uint32_t* r, uint32_t addr) {
    asm volatile("ldmatrix.sync.aligned.m8n8.x4.shared.b16 {%0,%1,%2,%3}, [%4];"
        : "=r"(r[0]), "=r"(r[1]), "=r"(r[2]), "=r"(r[3]) : "r"(addr));
}
__device__ __forceinline__ void mma16816(float* d, const uint32_t* a, const uint32_t* b) {
    asm volatile("mma.sync.aligned.m16n8k16.row.col.f32.f16.f16.f32 "
        "{%0,%1,%2,%3}, {%4,%5,%6,%7}, {%8,%9}, {%0,%1,%2,%3};"
        : "+f"(d[0]), "+f"(d[1]), "+f"(d[2]), "+f"(d[3])
        : "r"(a[0]), "r"(a[1]), "r"(a[2]), "r"(a[3]), "r"(b[0]), "r"(b[1]));
}

__device__ __forceinline__ float fast_sigmoid(float x) { return 1.0f / (1.0f + __expf(-x)); }
__device__ __forceinline__ float fast_tanh(float x) {
    float e = __expf(-2.0f * fabsf(x));
    return copysignf((1.0f - e) / (1.0f + e), x);
}

// ---------------------------------------------------------------------------
// Merged pack kernel:
//   blocks [0, 8192)          : A = [x | h] fp16              (B*K/4 float4s)
//   blocks [8192, 24576)      : W fragment-linear fp16        (N*K/2 uint32s)
//   blocks [24576, 24592)     : bias
// ---------------------------------------------------------------------------
#define PACK_A_BLKS 8192
#define PACK_W_BLKS 16384
#define PACK_B_BLKS 16
#define PACK_BLKS (PACK_A_BLKS + PACK_W_BLKS + PACK_B_BLKS)

__global__ void pack_all_kernel(
    const float4* __restrict__ x, const float4* __restrict__ h,
    const float* __restrict__ Wxf, const float* __restrict__ Wxi,
    const float* __restrict__ Wxo, const float* __restrict__ Wxc,
    const float* __restrict__ Whf, const float* __restrict__ Whi,
    const float* __restrict__ Who, const float* __restrict__ Whc,
    const float* __restrict__ bxf, const float* __restrict__ bxi,
    const float* __restrict__ bxo, const float* __restrict__ bxc,
    const float* __restrict__ bhf, const float* __restrict__ bhi,
    const float* __restrict__ bho, const float* __restrict__ bhc) {
    const int bid = blockIdx.x;
    if (bid < PACK_A_BLKS) {
        int i = bid * 256 + threadIdx.x;             // over B*K/4
        int b = i >> 9, k4 = i & 511;
        float4 v = (k4 < 256) ? x[b * 256 + k4] : h[b * 256 + (k4 - 256)];
        __half2* A2 = reinterpret_cast<__half2*>(g_A);
        A2[i * 2]     = __halves2half2(__float2half(v.x), __float2half(v.y));
        A2[i * 2 + 1] = __halves2half2(__float2half(v.z), __float2half(v.w));
    } else if (bid < PACK_A_BLKS + PACK_W_BLKS) {
        int o = (bid - PACK_A_BLKS) * 256 + threadIdx.x;   // over N*K/2 uint32
        int jj   = o & 3;
        int lane = (o >> 2) & 31;
        int h2   = (o >> 7) & 1;
        int ks   = (o >> 8) & 127;
        int NB   = o >> 15;
        int n = NB * 32 + h2 * 16 + (jj >> 1) * 8 + (lane >> 2);
        int k = ks * 16 + (jj & 1) * 8 + 2 * (lane & 3);
        int g = n & 3, j = n >> 2;
        const float* Wx[4] = {Wxf, Wxi, Wxo, Wxc};
        const float* Wh[4] = {Whf, Whi, Who, Whc};
        // k is even and the [x|h] boundary (1024) is even: pair never straddles
        float2 v = (k < IN_DIM)
            ? reinterpret_cast<const float2*>(Wx[g])[j * (IN_DIM / 2) + (k >> 1)]
            : reinterpret_cast<const float2*>(Wh[g])[j * (H_DIM / 2) + ((k - IN_DIM) >> 1)];
        __half2 p = __halves2half2(__float2half(v.x), __float2half(v.y));
        reinterpret_cast<__half2*>(g_Wf)[o] = p;
    } else {
        int n = (bid - PACK_A_BLKS - PACK_W_BLKS) * 256 + threadIdx.x;
        int g = n & 3, j = n >> 2;
        const float* bx[4] = {bxf, bxi, bxo, bxc};
        const float* bh[4] = {bhf, bhi, bho, bhc};
        g_biasp[n] = bx[g][j] + bh[g][j];
    }
}

// ---------------------------------------------------------------------------
// HMMA GEMM + fused LSTM epilogue.
// 8 warps: warp grid 2(M) x 4(N); warp tile 64x32; mma m16n8k16 fp16.
// A: 4-stage cp.async smem pipeline + ldmatrix (2-deep frag pipeline).
// W: fragment-linear global layout, loaded straight to registers with two
//    coalesced LDG.128 per k-step (no smem traffic for W at all).
// ---------------------------------------------------------------------------
__global__ void __launch_bounds__(256, 2)
lstm_gemm_kernel(const float* __restrict__ c_in, float* __restrict__ out) {
    extern __shared__ char smem[];
    const uint32_t sb = smem_u32(smem);
    const int tid  = threadIdx.x;
    const int lane = tid & 31;
    const int wid  = tid >> 5;
    const int wm   = wid >> 2;         // 0..1
    const int wn   = wid & 3;          // 0..3
    const int m0   = blockIdx.y * BM;
    const int n0   = blockIdx.x * BN;

    // ---- A chunk loader: 4 x 16B cp.async per thread ----
    auto load_chunk = [&](int t, int stg) {
        const uint32_t base = sb + stg * ATILE;
        const int kg = t * KC;
        #pragma unroll
        for (int q = 0; q < 4; q++) {
            const int op = tid + q * 256;
            const int r = op >> 3, s = op & 7;
            cp_async16(base + (uint32_t)(r * ROWB + s * 16),
                       g_A + (size_t)(m0 + r) * K_DIM + kg + s * 8);
        }
        CP_COMMIT();
    };

    float acc[4][4][4];
    #pragma unroll
    for (int i = 0; i < 4; i++)
        #pragma unroll
        for (int j = 0; j < 4; j++)
            #pragma unroll
            for (int e = 0; e < 4; e++) acc[i][j][e] = 0.0f;

    // Prologue: fill 3 of 4 stages
    load_chunk(0, 0);
    load_chunk(1, 1);
    load_chunk(2, 2);

    // Loop-invariant A ldmatrix offsets
    const int a_row = lane & 15;
    const int a_col = (lane >> 4) * 16;
    uint32_t aoff[4];
    #pragma unroll
    for (int mi = 0; mi < 4; mi++)
        aoff[mi] = (uint32_t)((wm * 64 + mi * 16 + a_row) * ROWB + a_col);

    // W fragment pointer for this warp's n-block
    const int wNB = blockIdx.x * 4 + wn;
    const uint4* Wf4 = reinterpret_cast<const uint4*>(g_Wf)
                     + ((size_t)wNB * NKSTEP << 6) + lane;

    // Fragment double buffers
    uint32_t ah0[16], ah1[16], bb0[8], bb1[8];

    auto ld_a = [&](uint32_t stage_base, int s, uint32_t* ap) {
        const uint32_t hb = stage_base + (uint32_t)(s * 32);
        #pragma unroll
        for (int mi = 0; mi < 4; mi++) ldsm4(&ap[mi * 4], hb + aoff[mi]);
    };
    auto ld_w = [&](int ksg, uint32_t* bp) {
        const uint4* p = Wf4 + ((size_t)ksg << 6);
        uint4 q0 = __ldg(p);
        uint4 q1 = __ldg(p + 32);
        bp[0] = q0.x; bp[1] = q0.y; bp[2] = q0.z; bp[3] = q0.w;
        bp[4] = q1.x; bp[5] = q1.y; bp[6] = q1.z; bp[7] = q1.w;
    };
    auto do_mmas = [&](const uint32_t* ap, const uint32_t* bp) {
        #pragma unroll
        for (int mi = 0; mi < 4; mi++)
            #pragma unroll
            for (int nj = 0; nj < 4; nj++)
                mma16816(acc[mi][nj], &ap[mi * 4], &bp[(nj >> 1) * 4 + (nj & 1) * 2]);
    };

    // Steady-state invariant at loop top: chunk t's A stage visible,
    // A(t,0) in ah0, W(t,0) in bb0.
    CP_WAIT(2);
    __syncthreads();
    ld_w(0, bb0);
    ld_a(sb, 0, ah0);

    int stg = 0;
    for (int t = 0; t < NCHUNK; t++) {
        const uint32_t base = sb + stg * ATILE;
        const int nstg = (stg == NSTAGE - 1) ? 0 : stg + 1;
        const int ksg = t * 4;

        ld_w(ksg + 1, bb1);  ld_a(base, 1, ah1);  do_mmas(ah0, bb0);   // s0
        ld_w(ksg + 2, bb0);  ld_a(base, 2, ah0);  do_mmas(ah1, bb1);   // s1
        ld_w(ksg + 3, bb1);  ld_a(base, 3, ah1);  do_mmas(ah0, bb0);   // s2

        // Chunk t+1 complete for all threads; stage writes ordered.
        if (t < NCHUNK - 2) CP_WAIT(1); else CP_WAIT(0);
        __syncthreads();

        if (t + 3 < NCHUNK) load_chunk(t + 3, (t + 3) & (NSTAGE - 1));
        if (t + 1 < NCHUNK) {
            ld_w(ksg + 4, bb0);
            ld_a(sb + nstg * ATILE, 0, ah0);
        }
        do_mmas(ah1, bb1);                                              // s3
        stg = nstg;
    }

    // ---- fused LSTM epilogue, coalesced via smem transpose ----
    // Block owns rows m0..m0+127, hidden units u0..u0+31.
    __syncthreads();   // all pipeline smem reads done; reuse smem
    float* s_c  = reinterpret_cast<float*>(smem);
    float* s_ct = s_c + 128 * CPAD;
    float* s_ht = s_c + 2 * 128 * CPAD;
    const int u0 = n0 >> 2;

    // Coalesced load of previous cell state tile (128 rows x 32 units)
    #pragma unroll
    for (int it = 0; it < 4; it++) {
        int i = tid + it * 256;               // over 128*8 float4 slots
        int row = i >> 3, uq = i & 7;
        float4 v = *reinterpret_cast<const float4*>(
            c_in + (size_t)(m0 + row) * H_DIM + u0 + uq * 4);
        *reinterpret_cast<float4*>(s_c + row * CPAD + uq * 4) = v;
    }
    __syncthreads();

    // D frag: d0,d1 = row (lane>>2), cols q*2,q*2+1 ; d2,d3 = row+8 (q = lane&3)
    // q even lane holds (f,i), odd (o,c); shfl-xor(1) completes each unit.
    const bool fi = ((lane & 1) == 0);
    const int q = lane & 3;

    #pragma unroll
    for (int nj = 0; nj < 4; nj++) {
        const int nb = n0 + wn * 32 + nj * 8 + q * 2;
        const float b0 = g_biasp[nb];
        const float b1 = g_biasp[nb + 1];
        const int ul = wn * 8 + nj * 2 + (q >> 1);   // local unit 0..31
        #pragma unroll
        for (int mi = 0; mi < 4; mi++) {
            const int rbase = wm * 64 + mi * 16 + (lane >> 2);
            float z0 = acc[mi][nj][0] + b0;
            float z1 = acc[mi][nj][1] + b1;
            float z2 = acc[mi][nj][2] + b0;
            float z3 = acc[mi][nj][3] + b1;
            float v0 = fast_sigmoid(z0);
            float v1 = fi ? fast_sigmoid(z1) : fast_tanh(z1);
            float v2 = fast_sigmoid(z2);
            float v3 = fi ? fast_sigmoid(z3) : fast_tanh(z3);
            float s0 = fi ? v2 : v0;
            float s1 = fi ? v3 : v1;
            float r0 = __shfl_xor_sync(0xffffffffu, s0, 1);
            float r1 = __shfl_xor_sync(0xffffffffu, s1, 1);
            const int row = rbase + (fi ? 0 : 8);
            float gf = fi ? v0 : r0;
            float gi = fi ? v1 : r1;
            float go = fi ? r0 : v2;
            float gc = fi ? r1 : v3;
            float cp = s_c[row * CPAD + ul];
            float ct = gf * cp + gc * gi;
            float ht = fast_tanh(ct) * go;
            s_ct[row * CPAD + ul] = ct;
            s_ht[row * CPAD + ul] = ht;
        }
    }
    __syncthreads();

    // Coalesced global writes
    float* ht_base = out + (size_t)B_DIM * H_DIM;
    #pragma unroll
    for (int it = 0; it < 4; it++) {
        int i = tid + it * 256;
        int row = i >> 3, uq = i & 7;
        *reinterpret_cast<float4*>(out + (size_t)(m0 + row) * H_DIM + u0 + uq * 4) =
            *reinterpret_cast<float4*>(s_ct + row * CPAD + uq * 4);
        *reinterpret_cast<float4*>(ht_base + (size_t)(m0 + row) * H_DIM + u0 + uq * 4) =
            *reinterpret_cast<float4*>(s_ht + row * CPAD + uq * 4);
    }
}

// ---------------------------------------------------------------------------
// kernel_launch
// Inputs: x, c, h, Wxf, bxf, Whf, bhf, Wxi, bxi, Whi, bhi,
//         Wxo, bxo, Who, bho, Wxc, bxc, Whc, bhc
// ---------------------------------------------------------------------------
extern "C" void kernel_launch(void* const* d_in, const int* in_sizes, int n_in,
                              void* d_out, int out_size) {
    const float* x   = (const float*)d_in[0];
    const float* c   = (const float*)d_in[1];
    const float* h   = (const float*)d_in[2];
    const float* Wxf = (const float*)d_in[3];
    const float* bxf = (const float*)d_in[4];
    const float* Whf = (const float*)d_in[5];
    const float* bhf = (const float*)d_in[6];
    const float* Wxi = (const float*)d_in[7];
    const float* bxi = (const float*)d_in[8];
    const float* Whi = (const float*)d_in[9];
    const float* bhi = (const float*)d_in[10];
    const float* Wxo = (const float*)d_in[11];
    const float* bxo = (const float*)d_in[12];
    const float* Who = (const float*)d_in[13];
    const float* bho = (const float*)d_in[14];
    const float* Wxc = (const float*)d_in[15];
    const float* bxc = (const float*)d_in[16];
    const float* Whc = (const float*)d_in[17];
    const float* bhc = (const float*)d_in[18];

    pack_all_kernel<<<PACK_BLKS, 256>>>(
        (const float4*)x, (const float4*)h,
        Wxf, Wxi, Wxo, Wxc, Whf, Whi, Who, Whc,
        bxf, bxi, bxo, bxc, bhf, bhi, bho, bhc);

    cudaFuncSetAttribute(lstm_gemm_kernel,
                         cudaFuncAttributeMaxDynamicSharedMemorySize, SMEM_TOTAL);
    dim3 grid(N_DIM / BN, B_DIM / BM);   // (32, 32)
    lstm_gemm_kernel<<<grid, 256, SMEM_TOTAL>>>(c, (float*)d_out);
}

// round 12
// speedup vs baseline: 1.2549x; 1.2549x over previous
#include <cuda_runtime.h>
#include <cuda_fp16.h>
#include <cstdint>
#include <math.h>

#define B_DIM 4096
#define IN_DIM 1024
#define H_DIM 1024
#define K_DIM 2048   // IN + H
#define N_DIM 4096   // 4*H, gate-interleaved: col n -> gate n&3, hidden n>>2

#define BM 128
#define BN 128
#define KC 64
#define NCHUNK (K_DIM / KC)     // 32

// SMEM tile rows: 64 fp16 = 128B data + 16B pad = 144B.
// 16B-lane of row r = 9r mod 8 -> distinct over 8 consecutive rows:
// conflict-free ldmatrix and cp.async.
#define ROWB 144
#define TILEB (128 * ROWB)            // 18432 B per matrix
#define OFF_A 0
#define OFF_W (TILEB)
#define BUFB  (2 * TILEB)             // 36864 B per stage
#define NSTAGE 3
#define SMEM_TOTAL (NSTAGE * BUFB)    // 110592 B

// Epilogue smem (reuses pipeline smem): 3 x [128][CPAD] fp32 = 55296 B
#define CPAD 36

// ---------------------------------------------------------------------------
// Device scratch
// ---------------------------------------------------------------------------
__device__ __half g_A[(size_t)B_DIM * K_DIM];
__device__ __half g_W[(size_t)N_DIM * K_DIM];
__device__ float g_biasp[N_DIM];

// ---------------------------------------------------------------------------
// PTX helpers (baseline PTX only: works on compute_103 virtual arch)
// ---------------------------------------------------------------------------
__device__ __forceinline__ uint32_t smem_u32(const void* p) {
    uint32_t a;
    asm("{ .reg .u64 t; cvta.to.shared.u64 t, %1; cvt.u32.u64 %0, t; }" : "=r"(a) : "l"(p));
    return a;
}
__device__ __forceinline__ void cp_async16(uint32_t dst, const void* src) {
    asm volatile("cp.async.cg.shared.global [%0], [%1], 16;" :: "r"(dst), "l"(src));
}
#define CP_COMMIT()  asm volatile("cp.async.commit_group;" ::: "memory")
#define CP_WAIT(N)   asm volatile("cp.async.wait_group %0;" :: "n"(N) : "memory")

__device__ __forceinline__ void ldsm4(uint32_t* r, uint32_t addr) {
    asm volatile("ldmatrix.sync.aligned.m8n8.x4.shared.b16 {%0,%1,%2,%3}, [%4];"
        : "=r"(r[0]), "=r"(r[1]), "=r"(r[2]), "=r"(r[3]) : "r"(addr));
}
__device__ __forceinline__ void mma16816(float* d, const uint32_t* a, const uint32_t* b) {
    asm volatile("mma.sync.aligned.m16n8k16.row.col.f32.f16.f16.f32 "
        "{%0,%1,%2,%3}, {%4,%5,%6,%7}, {%8,%9}, {%0,%1,%2,%3};"
        : "+f"(d[0]), "+f"(d[1]), "+f"(d[2]), "+f"(d[3])
        : "r"(a[0]), "r"(a[1]), "r"(a[2]), "r"(a[3]), "r"(b[0]), "r"(b[1]));
}

__device__ __forceinline__ float fast_sigmoid(float x) { return 1.0f / (1.0f + __expf(-x)); }
__device__ __forceinline__ float fast_tanh(float x) {
    float e = __expf(-2.0f * fabsf(x));
    return copysignf((1.0f - e) / (1.0f + e), x);
}

// ---------------------------------------------------------------------------
// Merged pack kernel:
//   blocks [0, 8192)          : A = [x | h] fp16          (B*K/4 float4s)
//   blocks [8192, 16384)      : W gate-interleaved fp16   (N*K/4 float4s)
//   blocks [16384, 16400)     : bias
// ---------------------------------------------------------------------------
#define PACK_A_BLKS 8192
#define PACK_W_BLKS 8192
#define PACK_B_BLKS 16
#define PACK_BLKS (PACK_A_BLKS + PACK_W_BLKS + PACK_B_BLKS)

__global__ void pack_all_kernel(
    const float4* __restrict__ x, const float4* __restrict__ h,
    const float4* __restrict__ Wxf, const float4* __restrict__ Wxi,
    const float4* __restrict__ Wxo, const float4* __restrict__ Wxc,
    const float4* __restrict__ Whf, const float4* __restrict__ Whi,
    const float4* __restrict__ Who, const float4* __restrict__ Whc,
    const float* __restrict__ bxf, const float* __restrict__ bxi,
    const float* __restrict__ bxo, const float* __restrict__ bxc,
    const float* __restrict__ bhf, const float* __restrict__ bhi,
    const float* __restrict__ bho, const float* __restrict__ bhc) {
    const int bid = blockIdx.x;
    if (bid < PACK_A_BLKS) {
        int i = bid * 256 + threadIdx.x;             // over B*K/4
        int b = i >> 9, k4 = i & 511;
        float4 v = (k4 < 256) ? x[b * 256 + k4] : h[b * 256 + (k4 - 256)];
        __half2* A2 = reinterpret_cast<__half2*>(g_A);
        A2[i * 2]     = __halves2half2(__float2half(v.x), __float2half(v.y));
        A2[i * 2 + 1] = __halves2half2(__float2half(v.z), __float2half(v.w));
    } else if (bid < PACK_A_BLKS + PACK_W_BLKS) {
        int i = (bid - PACK_A_BLKS) * 256 + threadIdx.x;   // over N*K/4
        int n = i >> 9, k4 = i & 511;
        int g = n & 3, j = n >> 2;
        const float4* Wx[4] = {Wxf, Wxi, Wxo, Wxc};
        const float4* Wh[4] = {Whf, Whi, Who, Whc};
        float4 v = (k4 < 256) ? Wx[g][j * 256 + k4] : Wh[g][j * 256 + (k4 - 256)];
        __half2* W2 = reinterpret_cast<__half2*>(g_W);
        W2[i * 2]     = __halves2half2(__float2half(v.x), __float2half(v.y));
        W2[i * 2 + 1] = __halves2half2(__float2half(v.z), __float2half(v.w));
    } else {
        int n = (bid - PACK_A_BLKS - PACK_W_BLKS) * 256 + threadIdx.x;
        int g = n & 3, j = n >> 2;
        const float* bx[4] = {bxf, bxi, bxo, bxc};
        const float* bh[4] = {bhf, bhi, bho, bhc};
        g_biasp[n] = bx[g][j] + bh[g][j];
    }
}

// ---------------------------------------------------------------------------
// HMMA GEMM + fused LSTM epilogue.
// 8 warps: warp grid 2(M) x 4(N); warp tile 64x32; mma m16n8k16 fp16.
// KC=64 chunks; 3-stage cp.async pipeline + 2-deep register fragment pipeline.
// Anti-phase: the odd co-resident CTA (bid/148 parity) delays ~half a chunk
// once, so the two CTAs sharing an SM interleave their barrier/load windows
// instead of idling the SMSPs simultaneously.
// ---------------------------------------------------------------------------
__global__ void __launch_bounds__(256, 2)
lstm_gemm_kernel(const float* __restrict__ c_in, float* __restrict__ out) {
    extern __shared__ char smem[];
    const uint32_t sb = smem_u32(smem);
    const int tid  = threadIdx.x;
    const int lane = tid & 31;
    const int wid  = tid >> 5;
    const int wm   = wid >> 2;         // 0..1
    const int wn   = wid & 3;          // 0..3
    const int m0   = blockIdx.y * BM;
    const int n0   = blockIdx.x * BN;

    // ---- chunk loader: 8 x 16B cp.async per thread (A 4, W 4) ----
    auto load_chunk = [&](int t, int stg) {
        const uint32_t base = sb + stg * BUFB;
        const int kg = t * KC;
        #pragma unroll
        for (int q = 0; q < 4; q++) {
            const int op = tid + q * 256;
            const int r = op >> 3, s = op & 7;
            const uint32_t so = (uint32_t)(r * ROWB + s * 16);
            cp_async16(base + OFF_A + so, g_A + (size_t)(m0 + r) * K_DIM + kg + s * 8);
            cp_async16(base + OFF_W + so, g_W + (size_t)(n0 + r) * K_DIM + kg + s * 8);
        }
        CP_COMMIT();
    };

    float acc[4][4][4];
    #pragma unroll
    for (int i = 0; i < 4; i++)
        #pragma unroll
        for (int j = 0; j < 4; j++)
            #pragma unroll
            for (int e = 0; e < 4; e++) acc[i][j][e] = 0.0f;

    // Prologue: fill NSTAGE stages (0,1,2)
    load_chunk(0, 0);
    load_chunk(1, 1);
    load_chunk(2, 2);

    // Anti-phase delay for the odd co-resident CTA slot (after loads are in
    // flight). Classic placement: bid and bid+148 share an SM; parity of
    // bid/148 distinguishes the pair. ~500ns ~ half a chunk period.
    {
        const int bidlin = blockIdx.y * gridDim.x + blockIdx.x;
        if ((bidlin / 148) & 1) __nanosleep(500);
    }

    // Loop-invariant ldmatrix offsets
    const int a_row = lane & 15;
    const int a_col = (lane >> 4) * 16;
    const int b_row = (lane & 7) + (lane >> 4) * 8;
    const int b_col = ((lane >> 3) & 1) * 16;
    uint32_t aoff[4], woff[2];
    #pragma unroll
    for (int mi = 0; mi < 4; mi++)
        aoff[mi] = (uint32_t)((wm * 64 + mi * 16 + a_row) * ROWB + a_col) + OFF_A;
    #pragma unroll
    for (int f = 0; f < 2; f++)
        woff[f] = (uint32_t)((wn * 32 + f * 16 + b_row) * ROWB + b_col) + OFF_W;

    // Fragment double buffers
    uint32_t ah0[16], ah1[16], bb0[8], bb1[8];

    auto ld_frags = [&](uint32_t base, int h, uint32_t* ap, uint32_t* bp) {
        const uint32_t hb = base + (uint32_t)(h * 32);
        #pragma unroll
        for (int mi = 0; mi < 4; mi++) ldsm4(&ap[mi * 4], hb + aoff[mi]);
        #pragma unroll
        for (int f = 0; f < 2; f++)    ldsm4(&bp[f * 4], hb + woff[f]);
    };
    auto do_mmas = [&](const uint32_t* ap, const uint32_t* bp) {
        #pragma unroll
        for (int mi = 0; mi < 4; mi++)
            #pragma unroll
            for (int nj = 0; nj < 4; nj++)
                mma16816(acc[mi][nj], &ap[mi * 4], &bp[(nj >> 1) * 4 + (nj & 1) * 2]);
    };

    // Steady-state invariant at loop top: chunk t visible, frags (t,0) in buf0.
    CP_WAIT(2);
    __syncthreads();
    ld_frags(sb, 0, ah0, bb0);

    int stg = 0;
    for (int t = 0; t < NCHUNK; t++) {
        const uint32_t base = sb + stg * BUFB;
        const int nstg = (stg == NSTAGE - 1) ? 0 : stg + 1;

        ld_frags(base, 1, ah1, bb1);  do_mmas(ah0, bb0);   // (t,0)
        ld_frags(base, 2, ah0, bb0);  do_mmas(ah1, bb1);   // (t,1)
        ld_frags(base, 3, ah1, bb1);  do_mmas(ah0, bb0);   // (t,2)

        // Own cp.async groups: leave <=1 pending -> chunk t+1 complete for all
        // threads, then barrier (also closes reads of stage stg for rewrite).
        if (t < NCHUNK - 2) CP_WAIT(1); else CP_WAIT(0);
        __syncthreads();

        if (t + 3 < NCHUNK) load_chunk(t + 3, stg);   // (t+3)%3 == t%3
        if (t + 1 < NCHUNK) ld_frags(sb + nstg * BUFB, 0, ah0, bb0);
        do_mmas(ah1, bb1);                                  // (t,3)
        stg = nstg;
    }

    // ---- fused LSTM epilogue, coalesced via smem transpose ----
    // Block owns rows m0..m0+127, hidden units u0..u0+31.
    __syncthreads();   // all pipeline smem reads done; reuse smem
    float* s_c  = reinterpret_cast<float*>(smem);
    float* s_ct = s_c + 128 * CPAD;
    float* s_ht = s_c + 2 * 128 * CPAD;
    const int u0 = n0 >> 2;

    // Coalesced load of previous cell state tile (128 rows x 32 units)
    #pragma unroll
    for (int it = 0; it < 4; it++) {
        int i = tid + it * 256;               // over 128*8 float4 slots
        int row = i >> 3, uq = i & 7;
        float4 v = *reinterpret_cast<const float4*>(
            c_in + (size_t)(m0 + row) * H_DIM + u0 + uq * 4);
        *reinterpret_cast<float4*>(s_c + row * CPAD + uq * 4) = v;
    }
    __syncthreads();

    // D frag: d0,d1 = row (lane>>2), cols q*2,q*2+1 ; d2,d3 = row+8 (q = lane&3)
    // q even lane holds (f,i), odd (o,c); shfl-xor(1) completes each unit.
    const bool fi = ((lane & 1) == 0);
    const int q = lane & 3;

    #pragma unroll
    for (int nj = 0; nj < 4; nj++) {
        const int nb = n0 + wn * 32 + nj * 8 + q * 2;
        const float b0 = g_biasp[nb];
        const float b1 = g_biasp[nb + 1];
        const int ul = wn * 8 + nj * 2 + (q >> 1);   // local unit 0..31
        #pragma unroll
        for (int mi = 0; mi < 4; mi++) {
            const int rbase = wm * 64 + mi * 16 + (lane >> 2);
            float z0 = acc[mi][nj][0] + b0;
            float z1 = acc[mi][nj][1] + b1;
            float z2 = acc[mi][nj][2] + b0;
            float z3 = acc[mi][nj][3] + b1;
            float v0 = fast_sigmoid(z0);
            float v1 = fi ? fast_sigmoid(z1) : fast_tanh(z1);
            float v2 = fast_sigmoid(z2);
            float v3 = fi ? fast_sigmoid(z3) : fast_tanh(z3);
            float s0 = fi ? v2 : v0;
            float s1 = fi ? v3 : v1;
            float r0 = __shfl_xor_sync(0xffffffffu, s0, 1);
            float r1 = __shfl_xor_sync(0xffffffffu, s1, 1);
            const int row = rbase + (fi ? 0 : 8);
            float gf = fi ? v0 : r0;
            float gi = fi ? v1 : r1;
            float go = fi ? r0 : v2;
            float gc = fi ? r1 : v3;
            float cp = s_c[row * CPAD + ul];
            float ct = gf * cp + gc * gi;
            float ht = fast_tanh(ct) * go;
            s_ct[row * CPAD + ul] = ct;
            s_ht[row * CPAD + ul] = ht;
        }
    }
    __syncthreads();

    // Coalesced global writes
    float* ht_base = out + (size_t)B_DIM * H_DIM;
    #pragma unroll
    for (int it = 0; it < 4; it++) {
        int i = tid + it * 256;
        int row = i >> 3, uq = i & 7;
        *reinterpret_cast<float4*>(out + (size_t)(m0 + row) * H_DIM + u0 + uq * 4) =
            *reinterpret_cast<float4*>(s_ct + row * CPAD + uq * 4);
        *reinterpret_cast<float4*>(ht_base + (size_t)(m0 + row) * H_DIM + u0 + uq * 4) =
            *reinterpret_cast<float4*>(s_ht + row * CPAD + uq * 4);
    }
}

// ---------------------------------------------------------------------------
// kernel_launch
// Inputs: x, c, h, Wxf, bxf, Whf, bhf, Wxi, bxi, Whi, bhi,
//         Wxo, bxo, Who, bho, Wxc, bxc, Whc, bhc
// ---------------------------------------------------------------------------
extern "C" void kernel_launch(void* const* d_in, const int* in_sizes, int n_in,
                              void* d_out, int out_size) {
    const float* x   = (const float*)d_in[0];
    const float* c   = (const float*)d_in[1];
    const float* h   = (const float*)d_in[2];
    const float* Wxf = (const float*)d_in[3];
    const float* bxf = (const float*)d_in[4];
    const float* Whf = (const float*)d_in[5];
    const float* bhf = (const float*)d_in[6];
    const float* Wxi = (const float*)d_in[7];
    const float* bxi = (const float*)d_in[8];
    const float* Whi = (const float*)d_in[9];
    const float* bhi = (const float*)d_in[10];
    const float* Wxo = (const float*)d_in[11];
    const float* bxo = (const float*)d_in[12];
    const float* Who = (const float*)d_in[13];
    const float* bho = (const float*)d_in[14];
    const float* Wxc = (const float*)d_in[15];
    const float* bxc = (const float*)d_in[16];
    const float* Whc = (const float*)d_in[17];
    const float* bhc = (const float*)d_in[18];

    pack_all_kernel<<<PACK_BLKS, 256>>>(
        (const float4*)x, (const float4*)h,
        (const float4*)Wxf, (const float4*)Wxi, (const float4*)Wxo, (const float4*)Wxc,
        (const float4*)Whf, (const float4*)Whi, (const float4*)Who, (const float4*)Whc,
        bxf, bxi, bxo, bxc, bhf, bhi, bho, bhc);

    cudaFuncSetAttribute(lstm_gemm_kernel,
                         cudaFuncAttributeMaxDynamicSharedMemorySize, SMEM_TOTAL);
    dim3 grid(N_DIM / BN, B_DIM / BM);   // (32, 32)
    lstm_gemm_kernel<<<grid, 256, SMEM_TOTAL>>>(c, (float*)d_out);
}